// round 5
// baseline (speedup 1.0000x reference)
#include <cuda_runtime.h>
#include <cuda_bf16.h>
#include <math.h>
#include <stdint.h>

// ---------------- problem constants ----------------
#define BATCH 4
#define T_LEN 4096
#define DIM 1024
#define DI 2048            // d_inner
#define DSTATE 16
#define KCONV 4
#define NSCALES 3
#define ROWS_FULL (BATCH * T_LEN)          // 16384
#define LN_EPS 1e-5f

// ---------------- scratch (__device__ globals; no allocation allowed) ------
__device__ __align__(16) float g_xz[ROWS_FULL * 2 * DI];        // (x_in | gate)
__device__ __align__(16) float g_xc[ROWS_FULL * DI];            // conv+silu output
__device__ __align__(16) float g_bssm[ROWS_FULL * DSTATE];
__device__ __align__(16) float g_ys0[ROWS_FULL * DI];           // scale 0 ssm out
__device__ __align__(16) float g_ys1[(ROWS_FULL / 2) * DI];     // scale 1
__device__ __align__(16) float g_ys2[(ROWS_FULL / 4) * DI];     // scale 2
__device__ __align__(16) float g_fused[ROWS_FULL * DI];
__device__ __align__(16) float g_ctx[ROWS_FULL * DI];           // stored tf32-rounded
__device__ __align__(16) float g_h[ROWS_FULL * (DI / 2)];       // stored tf32-rounded
__device__ __align__(16) float g_mmin[ROWS_FULL * DI];          // stored tf32-rounded
__device__ __align__(16) float g_preln[ROWS_FULL * DIM];
__device__ __align__(16) float g_xcvt[ROWS_FULL * DIM];         // x rounded to tf32
__device__ __align__(16) float g_wcvt[DIM * 2 * DI + DI * (DI / 2) + (DI / 2) * DI + DI * DIM];
__device__ float g_sw[NSCALES];

// ---------------- helpers ----------------
__device__ __forceinline__ float sigmoidf(float x) { return 1.f / (1.f + expf(-x)); }
__device__ __forceinline__ float siluf(float x)    { return x / (1.f + expf(-x)); }
__device__ __forceinline__ float softplusf(float x){ return x > 20.f ? x : log1pf(expf(x)); }

__device__ __forceinline__ float f2tf32(float f) {
    uint32_t u;
    asm("cvt.rna.tf32.f32 %0, %1;" : "=r"(u) : "f"(f));
    return __uint_as_float(u);
}

__device__ __forceinline__ void mma_tf32(float* c, const float* a, float b0, float b1) {
    asm volatile(
        "mma.sync.aligned.m16n8k8.row.col.f32.tf32.tf32.f32 "
        "{%0,%1,%2,%3}, {%4,%5,%6,%7}, {%8,%9}, {%0,%1,%2,%3};\n"
        : "+f"(c[0]), "+f"(c[1]), "+f"(c[2]), "+f"(c[3])
        : "r"(__float_as_uint(a[0])), "r"(__float_as_uint(a[1])),
          "r"(__float_as_uint(a[2])), "r"(__float_as_uint(a[3])),
          "r"(__float_as_uint(b0)), "r"(__float_as_uint(b1)));
}

__device__ __forceinline__ void cp_async16(uint32_t saddr, const void* gaddr) {
    asm volatile("cp.async.ca.shared.global [%0], [%1], 16;\n" :: "r"(saddr), "l"(gaddr));
}
__device__ __forceinline__ void cp_commit() {
    asm volatile("cp.async.commit_group;\n");
}
template<int N>
__device__ __forceinline__ void cp_wait() {
    asm volatile("cp.async.wait_group %0;\n" :: "n"(N));
}

// ---------------- softmax over 3 scale weights ----------------
__global__ void softmax3_kernel(const float* __restrict__ sw) {
    float a = sw[0], b = sw[1], c = sw[2];
    float m = fmaxf(a, fmaxf(b, c));
    float ea = expf(a - m), eb = expf(b - m), ec = expf(c - m);
    float inv = 1.f / (ea + eb + ec);
    g_sw[0] = ea * inv; g_sw[1] = eb * inv; g_sw[2] = ec * inv;
}

// ---------------- f32 -> tf32-bit rounding pass ----------------
__global__ void cvt_tf32_kernel(const float* __restrict__ in, float* __restrict__ out, int n4) {
    int i = blockIdx.x * blockDim.x + threadIdx.x;
    if (i >= n4) return;
    float4 v = ((const float4*)in)[i];
    v.x = f2tf32(v.x); v.y = f2tf32(v.y); v.z = f2tf32(v.z); v.w = f2tf32(v.w);
    ((float4*)out)[i] = v;
}

// ---------------- TF32 tensor-core GEMM, cp.async double-buffered ----------
// C[M,N] = A[M,K] * B[K,N], row-major. M%128==0, N%128==0, K%32==0.
// A,B must contain tf32-rounded bits already.
// Block tile 128x128, K-tile 32, 256 threads = 8 warps of 64(m)x32(n).
// EPI: 0=store, 1=tf32(silu), 2=tf32(sigmoid(acc)*e1*silu(e2[row*4096+col])),
//      3=acc + e1[row*N+col]
#define AS_STRIDE 36
#define BS_STRIDE 136
#define AS_TILE (128 * AS_STRIDE)
#define BS_TILE (32 * BS_STRIDE)
#define SMEM_FLOATS (2 * AS_TILE + 2 * BS_TILE)
#define SMEM_BYTES (SMEM_FLOATS * 4)

template<int EPI>
__global__ __launch_bounds__(256, 2)
void tgemm_kernel(const float* __restrict__ A, const float* __restrict__ B,
                  float* __restrict__ C, int M, int N, int K,
                  const float* __restrict__ e1, const float* __restrict__ e2) {
    extern __shared__ float sm[];
    float* As = sm;                   // [2][128][36]
    float* Bs = sm + 2 * AS_TILE;     // [2][32][136]
    uint32_t As_u = (uint32_t)__cvta_generic_to_shared(As);
    uint32_t Bs_u = (uint32_t)__cvta_generic_to_shared(Bs);

    const int tid  = threadIdx.x;
    const int warp = tid >> 5;
    const int lane = tid & 31;
    const int wm = warp >> 2;          // 0..1
    const int wn = warp & 3;           // 0..3
    const int g  = lane >> 2;          // 0..7
    const int tg = lane & 3;           // 0..3

    const int m0 = blockIdx.y * 128;
    const int n0 = blockIdx.x * 128;

    // per-thread load coords
    const int lar  = tid >> 3;              // A row (+256/8=32 per it)
    const int lac4 = (tid & 7) * 4;         // A col
    const int lbk  = tid >> 5;              // B k  (+8 per it)
    const int lbn4 = (tid & 31) * 4;        // B n

    float acc[4][4][4];
#pragma unroll
    for (int i = 0; i < 4; i++)
#pragma unroll
        for (int j = 0; j < 4; j++)
#pragma unroll
            for (int q = 0; q < 4; q++) acc[i][j][q] = 0.f;

    const int KT = K >> 5;

    // issue tile 0
#pragma unroll
    for (int it = 0; it < 4; it++) {
        int r = lar + it * 32;
        cp_async16(As_u + (r * AS_STRIDE + lac4) * 4, &A[(size_t)(m0 + r) * K + lac4]);
        int kk = lbk + it * 8;
        cp_async16(Bs_u + (kk * BS_STRIDE + lbn4) * 4, &B[(size_t)kk * N + n0 + lbn4]);
    }
    cp_commit();

    for (int kt = 0; kt < KT; kt++) {
        int st = kt & 1;
        if (kt + 1 < KT) {
            int k0 = (kt + 1) << 5;
            int so = ((kt + 1) & 1);
#pragma unroll
            for (int it = 0; it < 4; it++) {
                int r = lar + it * 32;
                cp_async16(As_u + (so * AS_TILE + r * AS_STRIDE + lac4) * 4,
                           &A[(size_t)(m0 + r) * K + k0 + lac4]);
                int kk = lbk + it * 8;
                cp_async16(Bs_u + (so * BS_TILE + kk * BS_STRIDE + lbn4) * 4,
                           &B[(size_t)(k0 + kk) * N + n0 + lbn4]);
            }
            cp_commit();
            cp_wait<1>();
        } else {
            cp_wait<0>();
        }
        __syncthreads();

        const float* Ast = As + st * AS_TILE;
        const float* Bst = Bs + st * BS_TILE;

#pragma unroll
        for (int ki = 0; ki < 4; ki++) {
            float bf[4][2];
#pragma unroll
            for (int ni = 0; ni < 4; ni++) {
                int n = wn * 32 + ni * 8 + g;
                bf[ni][0] = Bst[(ki * 8 + tg) * BS_STRIDE + n];
                bf[ni][1] = Bst[(ki * 8 + tg + 4) * BS_STRIDE + n];
            }
            float af[4][4];
#pragma unroll
            for (int mi = 0; mi < 4; mi++) {
                int r = wm * 64 + mi * 16 + g;
                af[mi][0] = Ast[(size_t)r * AS_STRIDE + ki * 8 + tg];
                af[mi][1] = Ast[(size_t)(r + 8) * AS_STRIDE + ki * 8 + tg];
                af[mi][2] = Ast[(size_t)r * AS_STRIDE + ki * 8 + tg + 4];
                af[mi][3] = Ast[(size_t)(r + 8) * AS_STRIDE + ki * 8 + tg + 4];
            }
#pragma unroll
            for (int mi = 0; mi < 4; mi++)
#pragma unroll
                for (int ni = 0; ni < 4; ni++)
                    mma_tf32(acc[mi][ni], af[mi], bf[ni][0], bf[ni][1]);
        }
        __syncthreads();
    }

    // ---- epilogue ----
#pragma unroll
    for (int mi = 0; mi < 4; mi++) {
#pragma unroll
        for (int ni = 0; ni < 4; ni++) {
            int r0 = m0 + wm * 64 + mi * 16 + g;
            int cb = n0 + wn * 32 + ni * 8 + tg * 2;
#pragma unroll
            for (int half = 0; half < 2; half++) {
                int row = r0 + half * 8;
                float v0 = acc[mi][ni][half * 2 + 0];
                float v1 = acc[mi][ni][half * 2 + 1];
                size_t idx = (size_t)row * N + cb;
                float o0, o1;
                if (EPI == 0) {
                    o0 = v0; o1 = v1;
                } else if (EPI == 1) {
                    o0 = f2tf32(siluf(v0)); o1 = f2tf32(siluf(v1));
                } else if (EPI == 2) {
                    float g0 = e2[(size_t)row * (2 * DI) + cb];
                    float g1 = e2[(size_t)row * (2 * DI) + cb + 1];
                    o0 = f2tf32(e1[idx] * sigmoidf(v0) * siluf(g0));
                    o1 = f2tf32(e1[idx + 1] * sigmoidf(v1) * siluf(g1));
                } else {
                    o0 = v0 + e1[idx];
                    o1 = v1 + e1[idx + 1];
                }
                *(float2*)&C[idx] = make_float2(o0, o1);
            }
        }
    }
}

// ---------------- causal depthwise conv (K=4) + silu, fused downsample ------
// Reads x_in directly from xz (row stride 2*DI), mean-pooling `stride` rows.
__global__ void conv_silu_kernel(const float* __restrict__ xz,
                                 const float* __restrict__ w, const float* __restrict__ b,
                                 float* __restrict__ xc, int Ts, int stride) {
    int idx = blockIdx.x * blockDim.x + threadIdx.x;
    int total = BATCH * Ts * DI;
    if (idx >= total) return;
    int c = idx & (DI - 1);
    int rt = idx / DI;
    int t = rt % Ts;
    int bb = rt / Ts;
    float inv = 1.f / (float)stride;
    float acc = b[c];
#pragma unroll
    for (int k = 0; k < KCONV; k++) {
        int tt = t - (KCONV - 1) + k;
        if (tt >= 0) {
            float v = 0.f;
            for (int r = 0; r < stride; r++)
                v += xz[(size_t)(bb * T_LEN + tt * stride + r) * (2 * DI) + c];
            acc = fmaf(w[c * KCONV + k], v * inv, acc);
        }
    }
    xc[idx] = siluf(acc);
}

// ---------------- B_ssm = xc @ xproj[:, :16] ----------------
__global__ __launch_bounds__(256)
void bssm_kernel(const float* __restrict__ xc, const float* __restrict__ xproj,
                 float* __restrict__ bssm) {
    __shared__ float xs[16][64];
    __shared__ float ws[64][16];
    int row0 = blockIdx.x * 16;
    int r = threadIdx.x >> 4;
    int j = threadIdx.x & 15;
    float acc = 0.f;
    for (int k0 = 0; k0 < DI; k0 += 64) {
        int v = threadIdx.x;
        int lr = v >> 4;
        int lc4 = (v & 15) * 4;
        *(float4*)&xs[lr][lc4] = *(const float4*)&xc[(size_t)(row0 + lr) * DI + k0 + lc4];
#pragma unroll
        for (int it = 0; it < 4; it++) {
            int kk = it * 16 + (threadIdx.x >> 4);
            int jj = threadIdx.x & 15;
            ws[kk][jj] = xproj[(size_t)(k0 + kk) * (2 * DSTATE) + jj];
        }
        __syncthreads();
#pragma unroll
        for (int kk = 0; kk < 64; kk++) acc = fmaf(xs[r][kk], ws[kk][j], acc);
        __syncthreads();
    }
    bssm[(size_t)(row0 + r) * DSTATE + j] = acc;
}

// ---------------- SSM pointwise (fused downsample for the D*x term) --------
__global__ __launch_bounds__(256)
void ssm_pw_kernel(const float* __restrict__ xc, const float* __restrict__ bssm,
                   const float* __restrict__ dtw, const float* __restrict__ dtb,
                   const float* __restrict__ D, const float* __restrict__ xz,
                   int Ts, int stride, float* __restrict__ ys) {
    int row = blockIdx.x;
    int t = row % Ts;
    int bb = row / Ts;
    float inv = 1.f / (float)stride;
    __shared__ float bs[DSTATE];
    if (threadIdx.x < DSTATE) bs[threadIdx.x] = bssm[(size_t)row * DSTATE + threadIdx.x];
    __syncthreads();
    for (int c = threadIdx.x; c < DI; c += 256) {
        float dt = dtb[c];
#pragma unroll
        for (int k = 0; k < DSTATE; k++) dt = fmaf(bs[k], dtw[k * DI + c], dt);
        float sg = sigmoidf(softplusf(dt));
        float xv = 0.f;
        for (int r = 0; r < stride; r++)
            xv += xz[(size_t)(bb * T_LEN + t * stride + r) * (2 * DI) + c];
        xv *= inv;
        ys[(size_t)row * DI + c] = xc[(size_t)row * DI + c] * sg + D[c] * xv;
    }
}

// ---------------- merged upsample + fuse (all 3 scales in one pass) ----------
__global__ void ups_fuse_kernel(const float* __restrict__ ys0,
                                const float* __restrict__ ys1,
                                const float* __restrict__ ys2,
                                float* __restrict__ fused, float* __restrict__ ctx) {
    int idx = blockIdx.x * blockDim.x + threadIdx.x;
    const int total4 = ROWS_FULL * (DI / 4);
    if (idx >= total4) return;
    int c4 = (idx & (DI / 4 - 1)) * 4;
    int rt = idx / (DI / 4);
    int t = rt % T_LEN;
    int bb = rt / T_LEN;

    float4 v0 = *(const float4*)&ys0[(size_t)(bb * T_LEN + t) * DI + c4];

    float4 v1, v2;
    {   // scale 1: Ts = 2048
        const int Ts = T_LEN / 2;
        float coord = (t + 0.5f) * 0.5f - 0.5f;
        coord = fminf(fmaxf(coord, 0.f), (float)(Ts - 1));
        int lo = (int)floorf(coord);
        int hi = min(lo + 1, Ts - 1);
        float wf = coord - (float)lo;
        float4 a = *(const float4*)&ys1[(size_t)(bb * Ts + lo) * DI + c4];
        float4 b = *(const float4*)&ys1[(size_t)(bb * Ts + hi) * DI + c4];
        v1.x = a.x + (b.x - a.x) * wf; v1.y = a.y + (b.y - a.y) * wf;
        v1.z = a.z + (b.z - a.z) * wf; v1.w = a.w + (b.w - a.w) * wf;
    }
    {   // scale 2: Ts = 1024
        const int Ts = T_LEN / 4;
        float coord = (t + 0.5f) * 0.25f - 0.5f;
        coord = fminf(fmaxf(coord, 0.f), (float)(Ts - 1));
        int lo = (int)floorf(coord);
        int hi = min(lo + 1, Ts - 1);
        float wf = coord - (float)lo;
        float4 a = *(const float4*)&ys2[(size_t)(bb * Ts + lo) * DI + c4];
        float4 b = *(const float4*)&ys2[(size_t)(bb * Ts + hi) * DI + c4];
        v2.x = a.x + (b.x - a.x) * wf; v2.y = a.y + (b.y - a.y) * wf;
        v2.z = a.z + (b.z - a.z) * wf; v2.w = a.w + (b.w - a.w) * wf;
    }

    float w0 = g_sw[0], w1 = g_sw[1], w2 = g_sw[2];
    float4 f, cx;
    f.x = w0 * v0.x + w1 * v1.x + w2 * v2.x;
    f.y = w0 * v0.y + w1 * v1.y + w2 * v2.y;
    f.z = w0 * v0.z + w1 * v1.z + w2 * v2.z;
    f.w = w0 * v0.w + w1 * v1.w + w2 * v2.w;
    const float third = 1.f / 3.f;
    // ctx feeds a GEMM only -> store tf32-rounded
    cx.x = f2tf32((v0.x + v1.x + v2.x) * third);
    cx.y = f2tf32((v0.y + v1.y + v2.y) * third);
    cx.z = f2tf32((v0.z + v1.z + v2.z) * third);
    cx.w = f2tf32((v0.w + v1.w + v2.w) * third);

    size_t o = (size_t)rt * DI + c4;
    *(float4*)&fused[o] = f;
    *(float4*)&ctx[o] = cx;
}

// ---------------- LayerNorm over last dim (1024) ----------------
__global__ __launch_bounds__(256)
void ln_kernel(const float* __restrict__ y, const float* __restrict__ g,
               const float* __restrict__ b, float* __restrict__ out) {
    int row = blockIdx.x;
    const float* yr = y + (size_t)row * DIM;
    float s = 0.f, s2 = 0.f;
    for (int c = threadIdx.x; c < DIM; c += 256) {
        float v = yr[c];
        s += v; s2 += v * v;
    }
#pragma unroll
    for (int o = 16; o > 0; o >>= 1) {
        s  += __shfl_down_sync(0xffffffffu, s, o);
        s2 += __shfl_down_sync(0xffffffffu, s2, o);
    }
    __shared__ float shs[8], shs2[8];
    __shared__ float smu, srstd;
    int wid = threadIdx.x >> 5, lane = threadIdx.x & 31;
    if (lane == 0) { shs[wid] = s; shs2[wid] = s2; }
    __syncthreads();
    if (wid == 0) {
        s  = lane < 8 ? shs[lane]  : 0.f;
        s2 = lane < 8 ? shs2[lane] : 0.f;
#pragma unroll
        for (int o = 4; o > 0; o >>= 1) {
            s  += __shfl_down_sync(0xffffffffu, s, o);
            s2 += __shfl_down_sync(0xffffffffu, s2, o);
        }
        if (lane == 0) {
            float mu = s / DIM;
            float var = s2 / DIM - mu * mu;
            smu = mu;
            srstd = rsqrtf(var + LN_EPS);
        }
    }
    __syncthreads();
    float mu = smu, rstd = srstd;
    for (int c = threadIdx.x; c < DIM; c += 256) {
        out[(size_t)row * DIM + c] = (yr[c] - mu) * rstd * g[c] + b[c];
    }
}

// ---------------- launch ----------------
extern "C" void kernel_launch(void* const* d_in, const int* in_sizes, int n_in,
                              void* d_out, int out_size) {
    const float* x        = (const float*)d_in[0];
    const float* in_proj  = (const float*)d_in[1];
    const float* conv_w   = (const float*)d_in[2];
    const float* conv_b   = (const float*)d_in[3];
    const float* xproj_w  = (const float*)d_in[4];
    const float* dtproj_w = (const float*)d_in[5];
    const float* dtproj_b = (const float*)d_in[6];
    const float* D_param  = (const float*)d_in[7];
    const float* scale_w  = (const float*)d_in[8];
    const float* cg_w1    = (const float*)d_in[9];
    const float* cg_w2    = (const float*)d_in[10];
    const float* out_proj = (const float*)d_in[11];
    const float* ln_g     = (const float*)d_in[12];
    const float* ln_b     = (const float*)d_in[13];
    float* out = (float*)d_out;

    float *p_xz, *p_xc, *p_bssm, *p_ys0, *p_ys1, *p_ys2,
          *p_fused, *p_ctx, *p_h, *p_mmin, *p_preln, *p_xcvt, *p_wcvt;
    cudaGetSymbolAddress((void**)&p_xz, g_xz);
    cudaGetSymbolAddress((void**)&p_xc, g_xc);
    cudaGetSymbolAddress((void**)&p_bssm, g_bssm);
    cudaGetSymbolAddress((void**)&p_ys0, g_ys0);
    cudaGetSymbolAddress((void**)&p_ys1, g_ys1);
    cudaGetSymbolAddress((void**)&p_ys2, g_ys2);
    cudaGetSymbolAddress((void**)&p_fused, g_fused);
    cudaGetSymbolAddress((void**)&p_ctx, g_ctx);
    cudaGetSymbolAddress((void**)&p_h, g_h);
    cudaGetSymbolAddress((void**)&p_mmin, g_mmin);
    cudaGetSymbolAddress((void**)&p_preln, g_preln);
    cudaGetSymbolAddress((void**)&p_xcvt, g_xcvt);
    cudaGetSymbolAddress((void**)&p_wcvt, g_wcvt);

    // tf32-bit weight copies, packed into g_wcvt
    float* p_w0 = p_wcvt;                                   // 1024 x 4096
    float* p_w1 = p_w0 + (size_t)DIM * 2 * DI;              // 2048 x 1024
    float* p_w2 = p_w1 + (size_t)DI * (DI / 2);             // 1024 x 2048
    float* p_w3 = p_w2 + (size_t)(DI / 2) * DI;             // 2048 x 1024

    cudaFuncSetAttribute(tgemm_kernel<0>, cudaFuncAttributeMaxDynamicSharedMemorySize, SMEM_BYTES);
    cudaFuncSetAttribute(tgemm_kernel<1>, cudaFuncAttributeMaxDynamicSharedMemorySize, SMEM_BYTES);
    cudaFuncSetAttribute(tgemm_kernel<2>, cudaFuncAttributeMaxDynamicSharedMemorySize, SMEM_BYTES);
    cudaFuncSetAttribute(tgemm_kernel<3>, cudaFuncAttributeMaxDynamicSharedMemorySize, SMEM_BYTES);

    softmax3_kernel<<<1, 1>>>(scale_w);

    // 0) round GEMM operands to tf32 bits
    {
        int n4;
        n4 = ROWS_FULL * DIM / 4;
        cvt_tf32_kernel<<<(n4 + 255) / 256, 256>>>(x, p_xcvt, n4);
        n4 = DIM * 2 * DI / 4;
        cvt_tf32_kernel<<<(n4 + 255) / 256, 256>>>(in_proj, p_w0, n4);
        n4 = DI * (DI / 2) / 4;
        cvt_tf32_kernel<<<(n4 + 255) / 256, 256>>>(cg_w1, p_w1, n4);
        n4 = (DI / 2) * DI / 4;
        cvt_tf32_kernel<<<(n4 + 255) / 256, 256>>>(cg_w2, p_w2, n4);
        n4 = DI * DIM / 4;
        cvt_tf32_kernel<<<(n4 + 255) / 256, 256>>>(out_proj, p_w3, n4);
    }

    // 1) xz = x @ in_proj_w   (16384 x 4096, K=1024)
    {
        dim3 grid(2 * DI / 128, ROWS_FULL / 128);
        tgemm_kernel<0><<<grid, 256, SMEM_BYTES>>>(p_xcvt, p_w0, p_xz,
                                                   ROWS_FULL, 2 * DI, DIM, nullptr, nullptr);
    }

    // 2) per-scale SSM path (downsample fused into conv / ssm_pw)
    float* ys_bufs[NSCALES] = {p_ys0, p_ys1, p_ys2};
    for (int s = 0; s < NSCALES; s++) {
        int stride = 1 << s;
        int Ts = T_LEN / stride;
        int rows = BATCH * Ts;
        int total = rows * DI;
        conv_silu_kernel<<<(total + 255) / 256, 256>>>(p_xz,
                                                       conv_w + (size_t)s * DI * KCONV,
                                                       conv_b + (size_t)s * DI,
                                                       p_xc, Ts, stride);
        bssm_kernel<<<rows / 16, 256>>>(p_xc, xproj_w + (size_t)s * DI * 2 * DSTATE, p_bssm);
        ssm_pw_kernel<<<rows, 256>>>(p_xc, p_bssm,
                                     dtproj_w + (size_t)s * DSTATE * DI,
                                     dtproj_b + (size_t)s * DI,
                                     D_param + (size_t)s * DI,
                                     p_xz, Ts, stride, ys_bufs[s]);
    }

    // 2b) merged upsample + fuse
    {
        int total4 = ROWS_FULL * (DI / 4);
        ups_fuse_kernel<<<(total4 + 255) / 256, 256>>>(p_ys0, p_ys1, p_ys2, p_fused, p_ctx);
    }

    // 3) h = tf32(silu(ctx @ cg_w1))   (16384 x 1024, K=2048)
    {
        dim3 grid((DI / 2) / 128, ROWS_FULL / 128);
        tgemm_kernel<1><<<grid, 256, SMEM_BYTES>>>(p_ctx, p_w1, p_h,
                                                   ROWS_FULL, DI / 2, DI, nullptr, nullptr);
    }
    // 4) mm_in = tf32(fused * sigmoid(h @ cg_w2) * silu(gate))  (16384 x 2048, K=1024)
    {
        dim3 grid(DI / 128, ROWS_FULL / 128);
        tgemm_kernel<2><<<grid, 256, SMEM_BYTES>>>(p_h, p_w2, p_mmin,
                                                   ROWS_FULL, DI, DI / 2, p_fused, p_xz + DI);
    }
    // 5) preln = mm_in @ out_proj + x   (16384 x 1024, K=2048)
    {
        dim3 grid(DIM / 128, ROWS_FULL / 128);
        tgemm_kernel<3><<<grid, 256, SMEM_BYTES>>>(p_mmin, p_w3, p_preln,
                                                   ROWS_FULL, DIM, DI, x, nullptr);
    }
    // 6) LayerNorm -> out
    ln_kernel<<<ROWS_FULL, 256>>>(p_preln, ln_g, ln_b, out);
}

// round 6
// speedup vs baseline: 1.1365x; 1.1365x over previous
#include <cuda_runtime.h>
#include <cuda_bf16.h>
#include <math.h>
#include <stdint.h>

// ---------------- problem constants ----------------
#define BATCH 4
#define T_LEN 4096
#define DIM 1024
#define DI 2048            // d_inner
#define DSTATE 16
#define KCONV 4
#define NSCALES 3
#define ROWS_FULL (BATCH * T_LEN)          // 16384
#define LN_EPS 1e-5f

// ---------------- scratch (__device__ globals; no allocation allowed) ------
__device__ __align__(16) float g_xz[ROWS_FULL * 2 * DI];        // (x_in | gate)
__device__ __align__(16) float g_xc[ROWS_FULL * DI];            // conv+silu output (tf32 bits)
__device__ __align__(16) float g_bssm[ROWS_FULL * 128];         // bssm GEMM out (padded N=128)
__device__ __align__(16) float g_bpad[DI * 128];                // zero-padded xproj (tf32 bits)
__device__ __align__(16) float g_ys0[ROWS_FULL * DI];           // scale 0 ssm out
__device__ __align__(16) float g_ys1[(ROWS_FULL / 2) * DI];     // scale 1
__device__ __align__(16) float g_ys2[(ROWS_FULL / 4) * DI];     // scale 2
__device__ __align__(16) float g_fused[ROWS_FULL * DI];
__device__ __align__(16) float g_ctx[ROWS_FULL * DI];           // tf32 bits
__device__ __align__(16) float g_h[ROWS_FULL * (DI / 2)];       // tf32 bits
__device__ __align__(16) float g_mmin[ROWS_FULL * DI];          // tf32 bits
__device__ __align__(16) float g_preln[ROWS_FULL * DIM];
__device__ __align__(16) float g_xcvt[ROWS_FULL * DIM];         // x tf32 bits
__device__ __align__(16) float g_wcvt[DIM * 2 * DI + DI * (DI / 2) + (DI / 2) * DI + DI * DIM];
__device__ float g_sw[NSCALES];

// ---------------- helpers ----------------
__device__ __forceinline__ float sigmoidf(float x) { return 1.f / (1.f + expf(-x)); }
__device__ __forceinline__ float siluf(float x)    { return x / (1.f + expf(-x)); }
__device__ __forceinline__ float softplusf(float x){ return x > 20.f ? x : log1pf(expf(x)); }

__device__ __forceinline__ float f2tf32(float f) {
    uint32_t u;
    asm("cvt.rna.tf32.f32 %0, %1;" : "=r"(u) : "f"(f));
    return __uint_as_float(u);
}

__device__ __forceinline__ void mma_tf32(float* c, const float* a, float b0, float b1) {
    asm volatile(
        "mma.sync.aligned.m16n8k8.row.col.f32.tf32.tf32.f32 "
        "{%0,%1,%2,%3}, {%4,%5,%6,%7}, {%8,%9}, {%0,%1,%2,%3};\n"
        : "+f"(c[0]), "+f"(c[1]), "+f"(c[2]), "+f"(c[3])
        : "r"(__float_as_uint(a[0])), "r"(__float_as_uint(a[1])),
          "r"(__float_as_uint(a[2])), "r"(__float_as_uint(a[3])),
          "r"(__float_as_uint(b0)), "r"(__float_as_uint(b1)));
}

// ---------------- softmax over 3 scale weights ----------------
__global__ void softmax3_kernel(const float* __restrict__ sw) {
    float a = sw[0], b = sw[1], c = sw[2];
    float m = fmaxf(a, fmaxf(b, c));
    float ea = expf(a - m), eb = expf(b - m), ec = expf(c - m);
    float inv = 1.f / (ea + eb + ec);
    g_sw[0] = ea * inv; g_sw[1] = eb * inv; g_sw[2] = ec * inv;
}

// ---------------- f32 -> tf32-bit rounding pass ----------------
__global__ void cvt_tf32_kernel(const float* __restrict__ in, float* __restrict__ out, int n4) {
    int i = blockIdx.x * blockDim.x + threadIdx.x;
    if (i >= n4) return;
    float4 v = ((const float4*)in)[i];
    v.x = f2tf32(v.x); v.y = f2tf32(v.y); v.z = f2tf32(v.z); v.w = f2tf32(v.w);
    ((float4*)out)[i] = v;
}

// ---------------- zero-pad xproj[:, :16] into [2048][128] tf32 ----------------
__global__ void pad_xproj_kernel(const float* __restrict__ xproj, float* __restrict__ bpad) {
    int i = blockIdx.x * blockDim.x + threadIdx.x;
    if (i >= DI * 128) return;
    int k = i >> 7, j = i & 127;
    bpad[i] = (j < DSTATE) ? f2tf32(xproj[k * 2 * DSTATE + j]) : 0.f;
}

// ---------------- TF32 tensor-core GEMM, double-buffered fragment-ready smem --
// C[M,N] = A[M,K] * B[K,N], row-major. M%128==0, N%128==0, K%32==0.
// A,B must already hold tf32-rounded bits.
// Block tile 128x128, K-tile 32, 256 threads = 8 warps of 64(m)x32(n).
// EPI: 0=store, 1=tf32(silu), 2=tf32(sigmoid(acc)*e1*silu(e2[row*4096+col])),
//      3=acc + e1[row*N+col]
#define AB_FLOATS (8 * 4 * 33 * 4)   // 4224 per buffer
#define BB_FLOATS (16 * 256)         // 4096 per buffer
#define SMEM_BYTES ((2 * AB_FLOATS + 2 * BB_FLOATS) * 4)

template<int EPI>
__global__ __launch_bounds__(256)
void tgemm_kernel(const float* __restrict__ A, const float* __restrict__ B,
                  float* __restrict__ C, int M, int N, int K,
                  const float* __restrict__ e1, const float* __restrict__ e2) {
    extern __shared__ float sm[];
    float* Asm = sm;                    // [2][AB_FLOATS]
    float* Bsm = sm + 2 * AB_FLOATS;    // [2][BB_FLOATS]

    const int tid  = threadIdx.x;
    const int warp = tid >> 5;
    const int lane = tid & 31;
    const int wm = warp >> 2;          // 0..1
    const int wn = warp & 3;           // 0..3
    const int g  = lane >> 2;          // 0..7
    const int tg = lane & 3;           // 0..3

    const int m0 = blockIdx.y * 128;
    const int n0 = blockIdx.x * 128;

    float acc[4][4][4];
#pragma unroll
    for (int i = 0; i < 4; i++)
#pragma unroll
        for (int j = 0; j < 4; j++)
#pragma unroll
            for (int q = 0; q < 4; q++) acc[i][j][q] = 0.f;

    float4 a_pre[4], b_pre[4];
    const int KT = K >> 5;

    // ---- prologue: load tile 0, scatter to buf0, load tile 1 ----
#pragma unroll
    for (int it = 0; it < 4; it++) {
        int v = tid + it * 256;
        int r = v >> 3, c4 = (v & 7) * 4;
        a_pre[it] = *(const float4*)&A[(size_t)(m0 + r) * K + c4];
        int kk = v >> 5, n4 = (v & 31) * 4;
        b_pre[it] = *(const float4*)&B[(size_t)kk * N + n0 + n4];
    }
    {
        float* Ab = Asm;
        float* Bb = Bsm;
#pragma unroll
        for (int it = 0; it < 4; it++) {
            int v = tid + it * 256;
            {
                int r = v >> 3, c4 = (v & 7) * 4;
                float va[4] = {a_pre[it].x, a_pre[it].y, a_pre[it].z, a_pre[it].w};
#pragma unroll
                for (int j = 0; j < 4; j++) {
                    int c = c4 + j;
                    int mi = r >> 4, rr = r & 15, ki = c >> 3, cc = c & 7;
                    int ls = (rr & 7) * 4 + (cc & 3);
                    int slot = (cc >> 2) * 2 + (rr >> 3);
                    Ab[((mi * 4 + ki) * 33 + ls) * 4 + slot] = va[j];
                }
            }
            {
                int kk = v >> 5, n4 = (v & 31) * 4;
                float vb[4] = {b_pre[it].x, b_pre[it].y, b_pre[it].z, b_pre[it].w};
#pragma unroll
                for (int j = 0; j < 4; j++) {
                    int nn = n4 + j;
                    int ni = nn >> 3, cc = nn & 7;
                    int ls = cc * 4 + (kk & 3);
                    int ki = kk >> 3;
                    int q = (ki & 1) * 2 + ((kk & 7) >> 2);
                    int lp = ls ^ (ni & 15);
                    int qp = q ^ (ni & 3);
                    Bb[ni * 256 + (ki >> 1) * 128 + lp * 4 + qp] = vb[j];
                }
            }
        }
    }
    if (KT > 1) {
#pragma unroll
        for (int it = 0; it < 4; it++) {
            int v = tid + it * 256;
            int r = v >> 3, c4 = (v & 7) * 4;
            a_pre[it] = *(const float4*)&A[(size_t)(m0 + r) * K + 32 + c4];
            int kk = v >> 5, n4 = (v & 31) * 4;
            b_pre[it] = *(const float4*)&B[(size_t)(32 + kk) * N + n0 + n4];
        }
    }
    __syncthreads();

    for (int kt = 0; kt < KT; kt++) {
        // ---- scatter next tile into the other buffer (overlaps compute) ----
        if (kt + 1 < KT) {
            int buf = (kt + 1) & 1;
            float* Ab = Asm + buf * AB_FLOATS;
            float* Bb = Bsm + buf * BB_FLOATS;
#pragma unroll
            for (int it = 0; it < 4; it++) {
                int v = tid + it * 256;
                {
                    int r = v >> 3, c4 = (v & 7) * 4;
                    float va[4] = {a_pre[it].x, a_pre[it].y, a_pre[it].z, a_pre[it].w};
#pragma unroll
                    for (int j = 0; j < 4; j++) {
                        int c = c4 + j;
                        int mi = r >> 4, rr = r & 15, ki = c >> 3, cc = c & 7;
                        int ls = (rr & 7) * 4 + (cc & 3);
                        int slot = (cc >> 2) * 2 + (rr >> 3);
                        Ab[((mi * 4 + ki) * 33 + ls) * 4 + slot] = va[j];
                    }
                }
                {
                    int kk = v >> 5, n4 = (v & 31) * 4;
                    float vb[4] = {b_pre[it].x, b_pre[it].y, b_pre[it].z, b_pre[it].w};
#pragma unroll
                    for (int j = 0; j < 4; j++) {
                        int nn = n4 + j;
                        int ni = nn >> 3, cc = nn & 7;
                        int ls = cc * 4 + (kk & 3);
                        int ki = kk >> 3;
                        int q = (ki & 1) * 2 + ((kk & 7) >> 2);
                        int lp = ls ^ (ni & 15);
                        int qp = q ^ (ni & 3);
                        Bb[ni * 256 + (ki >> 1) * 128 + lp * 4 + qp] = vb[j];
                    }
                }
            }
            // ---- prefetch tile kt+2 from global ----
            if (kt + 2 < KT) {
                int k0 = (kt + 2) << 5;
#pragma unroll
                for (int it = 0; it < 4; it++) {
                    int v = tid + it * 256;
                    int r = v >> 3, c4 = (v & 7) * 4;
                    a_pre[it] = *(const float4*)&A[(size_t)(m0 + r) * K + k0 + c4];
                    int kk = v >> 5, n4 = (v & 31) * 4;
                    b_pre[it] = *(const float4*)&B[(size_t)(k0 + kk) * N + n0 + n4];
                }
            }
        }

        // ---- compute from current buffer ----
        const float* Ast = Asm + (kt & 1) * AB_FLOATS;
        const float* Bst = Bsm + (kt & 1) * BB_FLOATS;
#pragma unroll
        for (int ki2 = 0; ki2 < 2; ki2++) {
            float bq[4][4];
#pragma unroll
            for (int ni = 0; ni < 4; ni++) {
                int ni_g = wn * 4 + ni;
                int lp = lane ^ (ni_g & 15);
                *(float4*)bq[ni] = *(const float4*)&Bst[ni_g * 256 + ki2 * 128 + lp * 4];
            }
#pragma unroll
            for (int h = 0; h < 2; h++) {
                int ki = ki2 * 2 + h;
                float af[4][4];
#pragma unroll
                for (int mi = 0; mi < 4; mi++) {
                    int mi_g = wm * 4 + mi;
                    *(float4*)af[mi] = *(const float4*)&Ast[((mi_g * 4 + ki) * 33 + lane) * 4];
                }
#pragma unroll
                for (int mi = 0; mi < 4; mi++)
#pragma unroll
                    for (int ni = 0; ni < 4; ni++) {
                        const int p = ni & 3;
                        float b0 = bq[ni][(h * 2 + 0) ^ p];
                        float b1 = bq[ni][(h * 2 + 1) ^ p];
                        mma_tf32(acc[mi][ni], af[mi], b0, b1);
                    }
            }
        }
        __syncthreads();
    }

    // ---- epilogue ----
#pragma unroll
    for (int mi = 0; mi < 4; mi++) {
#pragma unroll
        for (int ni = 0; ni < 4; ni++) {
            int r0 = m0 + wm * 64 + mi * 16 + g;
            int cb = n0 + wn * 32 + ni * 8 + tg * 2;
#pragma unroll
            for (int half = 0; half < 2; half++) {
                int row = r0 + half * 8;
                float v0 = acc[mi][ni][half * 2 + 0];
                float v1 = acc[mi][ni][half * 2 + 1];
                size_t idx = (size_t)row * N + cb;
                float o0, o1;
                if (EPI == 0) {
                    o0 = v0; o1 = v1;
                } else if (EPI == 1) {
                    o0 = f2tf32(siluf(v0)); o1 = f2tf32(siluf(v1));
                } else if (EPI == 2) {
                    float g0 = e2[(size_t)row * (2 * DI) + cb];
                    float g1 = e2[(size_t)row * (2 * DI) + cb + 1];
                    o0 = f2tf32(e1[idx] * sigmoidf(v0) * siluf(g0));
                    o1 = f2tf32(e1[idx + 1] * sigmoidf(v1) * siluf(g1));
                } else {
                    o0 = v0 + e1[idx];
                    o1 = v1 + e1[idx + 1];
                }
                *(float2*)&C[idx] = make_float2(o0, o1);
            }
        }
    }
}

// ---------------- causal depthwise conv (K=4) + silu, fused downsample ------
// Stores tf32-rounded (xc feeds a tensor GEMM).
__global__ void conv_silu_kernel(const float* __restrict__ xz,
                                 const float* __restrict__ w, const float* __restrict__ b,
                                 float* __restrict__ xc, int Ts, int stride) {
    int idx = blockIdx.x * blockDim.x + threadIdx.x;
    int total = BATCH * Ts * DI;
    if (idx >= total) return;
    int c = idx & (DI - 1);
    int rt = idx / DI;
    int t = rt % Ts;
    int bb = rt / Ts;
    float inv = 1.f / (float)stride;
    float acc = b[c];
#pragma unroll
    for (int k = 0; k < KCONV; k++) {
        int tt = t - (KCONV - 1) + k;
        if (tt >= 0) {
            float v = 0.f;
            for (int r = 0; r < stride; r++)
                v += xz[(size_t)(bb * T_LEN + tt * stride + r) * (2 * DI) + c];
            acc = fmaf(w[c * KCONV + k], v * inv, acc);
        }
    }
    xc[idx] = f2tf32(siluf(acc));
}

// ---------------- SSM pointwise (fused downsample for the D*x term) --------
// bssm now has row stride 128 (padded GEMM output), first 16 cols valid.
__global__ __launch_bounds__(256)
void ssm_pw_kernel(const float* __restrict__ xc, const float* __restrict__ bssm,
                   const float* __restrict__ dtw, const float* __restrict__ dtb,
                   const float* __restrict__ D, const float* __restrict__ xz,
                   int Ts, int stride, float* __restrict__ ys) {
    int row = blockIdx.x;
    int t = row % Ts;
    int bb = row / Ts;
    float inv = 1.f / (float)stride;
    __shared__ float bs[DSTATE];
    if (threadIdx.x < DSTATE) bs[threadIdx.x] = bssm[(size_t)row * 128 + threadIdx.x];
    __syncthreads();
    for (int c = threadIdx.x; c < DI; c += 256) {
        float dt = dtb[c];
#pragma unroll
        for (int k = 0; k < DSTATE; k++) dt = fmaf(bs[k], dtw[k * DI + c], dt);
        float sg = sigmoidf(softplusf(dt));
        float xv = 0.f;
        for (int r = 0; r < stride; r++)
            xv += xz[(size_t)(bb * T_LEN + t * stride + r) * (2 * DI) + c];
        xv *= inv;
        ys[(size_t)row * DI + c] = xc[(size_t)row * DI + c] * sg + D[c] * xv;
    }
}

// ---------------- merged upsample + fuse (all 3 scales in one pass) ----------
__global__ void ups_fuse_kernel(const float* __restrict__ ys0,
                                const float* __restrict__ ys1,
                                const float* __restrict__ ys2,
                                float* __restrict__ fused, float* __restrict__ ctx) {
    int idx = blockIdx.x * blockDim.x + threadIdx.x;
    const int total4 = ROWS_FULL * (DI / 4);
    if (idx >= total4) return;
    int c4 = (idx & (DI / 4 - 1)) * 4;
    int rt = idx / (DI / 4);
    int t = rt % T_LEN;
    int bb = rt / T_LEN;

    float4 v0 = *(const float4*)&ys0[(size_t)(bb * T_LEN + t) * DI + c4];

    float4 v1, v2;
    {   // scale 1: Ts = 2048
        const int Ts = T_LEN / 2;
        float coord = (t + 0.5f) * 0.5f - 0.5f;
        coord = fminf(fmaxf(coord, 0.f), (float)(Ts - 1));
        int lo = (int)floorf(coord);
        int hi = min(lo + 1, Ts - 1);
        float wf = coord - (float)lo;
        float4 a = *(const float4*)&ys1[(size_t)(bb * Ts + lo) * DI + c4];
        float4 b = *(const float4*)&ys1[(size_t)(bb * Ts + hi) * DI + c4];
        v1.x = a.x + (b.x - a.x) * wf; v1.y = a.y + (b.y - a.y) * wf;
        v1.z = a.z + (b.z - a.z) * wf; v1.w = a.w + (b.w - a.w) * wf;
    }
    {   // scale 2: Ts = 1024
        const int Ts = T_LEN / 4;
        float coord = (t + 0.5f) * 0.25f - 0.5f;
        coord = fminf(fmaxf(coord, 0.f), (float)(Ts - 1));
        int lo = (int)floorf(coord);
        int hi = min(lo + 1, Ts - 1);
        float wf = coord - (float)lo;
        float4 a = *(const float4*)&ys2[(size_t)(bb * Ts + lo) * DI + c4];
        float4 b = *(const float4*)&ys2[(size_t)(bb * Ts + hi) * DI + c4];
        v2.x = a.x + (b.x - a.x) * wf; v2.y = a.y + (b.y - a.y) * wf;
        v2.z = a.z + (b.z - a.z) * wf; v2.w = a.w + (b.w - a.w) * wf;
    }

    float w0 = g_sw[0], w1 = g_sw[1], w2 = g_sw[2];
    float4 f, cx;
    f.x = w0 * v0.x + w1 * v1.x + w2 * v2.x;
    f.y = w0 * v0.y + w1 * v1.y + w2 * v2.y;
    f.z = w0 * v0.z + w1 * v1.z + w2 * v2.z;
    f.w = w0 * v0.w + w1 * v1.w + w2 * v2.w;
    const float third = 1.f / 3.f;
    cx.x = f2tf32((v0.x + v1.x + v2.x) * third);
    cx.y = f2tf32((v0.y + v1.y + v2.y) * third);
    cx.z = f2tf32((v0.z + v1.z + v2.z) * third);
    cx.w = f2tf32((v0.w + v1.w + v2.w) * third);

    size_t o = (size_t)rt * DI + c4;
    *(float4*)&fused[o] = f;
    *(float4*)&ctx[o] = cx;
}

// ---------------- LayerNorm over last dim (1024) ----------------
__global__ __launch_bounds__(256)
void ln_kernel(const float* __restrict__ y, const float* __restrict__ g,
               const float* __restrict__ b, float* __restrict__ out) {
    int row = blockIdx.x;
    const float* yr = y + (size_t)row * DIM;
    float s = 0.f, s2 = 0.f;
    for (int c = threadIdx.x; c < DIM; c += 256) {
        float v = yr[c];
        s += v; s2 += v * v;
    }
#pragma unroll
    for (int o = 16; o > 0; o >>= 1) {
        s  += __shfl_down_sync(0xffffffffu, s, o);
        s2 += __shfl_down_sync(0xffffffffu, s2, o);
    }
    __shared__ float shs[8], shs2[8];
    __shared__ float smu, srstd;
    int wid = threadIdx.x >> 5, lane = threadIdx.x & 31;
    if (lane == 0) { shs[wid] = s; shs2[wid] = s2; }
    __syncthreads();
    if (wid == 0) {
        s  = lane < 8 ? shs[lane]  : 0.f;
        s2 = lane < 8 ? shs2[lane] : 0.f;
#pragma unroll
        for (int o = 4; o > 0; o >>= 1) {
            s  += __shfl_down_sync(0xffffffffu, s, o);
            s2 += __shfl_down_sync(0xffffffffu, s2, o);
        }
        if (lane == 0) {
            float mu = s / DIM;
            float var = s2 / DIM - mu * mu;
            smu = mu;
            srstd = rsqrtf(var + LN_EPS);
        }
    }
    __syncthreads();
    float mu = smu, rstd = srstd;
    for (int c = threadIdx.x; c < DIM; c += 256) {
        out[(size_t)row * DIM + c] = (yr[c] - mu) * rstd * g[c] + b[c];
    }
}

// ---------------- launch ----------------
extern "C" void kernel_launch(void* const* d_in, const int* in_sizes, int n_in,
                              void* d_out, int out_size) {
    const float* x        = (const float*)d_in[0];
    const float* in_proj  = (const float*)d_in[1];
    const float* conv_w   = (const float*)d_in[2];
    const float* conv_b   = (const float*)d_in[3];
    const float* xproj_w  = (const float*)d_in[4];
    const float* dtproj_w = (const float*)d_in[5];
    const float* dtproj_b = (const float*)d_in[6];
    const float* D_param  = (const float*)d_in[7];
    const float* scale_w  = (const float*)d_in[8];
    const float* cg_w1    = (const float*)d_in[9];
    const float* cg_w2    = (const float*)d_in[10];
    const float* out_proj = (const float*)d_in[11];
    const float* ln_g     = (const float*)d_in[12];
    const float* ln_b     = (const float*)d_in[13];
    float* out = (float*)d_out;

    float *p_xz, *p_xc, *p_bssm, *p_bpad, *p_ys0, *p_ys1, *p_ys2,
          *p_fused, *p_ctx, *p_h, *p_mmin, *p_preln, *p_xcvt, *p_wcvt;
    cudaGetSymbolAddress((void**)&p_xz, g_xz);
    cudaGetSymbolAddress((void**)&p_xc, g_xc);
    cudaGetSymbolAddress((void**)&p_bssm, g_bssm);
    cudaGetSymbolAddress((void**)&p_bpad, g_bpad);
    cudaGetSymbolAddress((void**)&p_ys0, g_ys0);
    cudaGetSymbolAddress((void**)&p_ys1, g_ys1);
    cudaGetSymbolAddress((void**)&p_ys2, g_ys2);
    cudaGetSymbolAddress((void**)&p_fused, g_fused);
    cudaGetSymbolAddress((void**)&p_ctx, g_ctx);
    cudaGetSymbolAddress((void**)&p_h, g_h);
    cudaGetSymbolAddress((void**)&p_mmin, g_mmin);
    cudaGetSymbolAddress((void**)&p_preln, g_preln);
    cudaGetSymbolAddress((void**)&p_xcvt, g_xcvt);
    cudaGetSymbolAddress((void**)&p_wcvt, g_wcvt);

    // tf32-bit weight copies, packed into g_wcvt
    float* p_w0 = p_wcvt;                                   // 1024 x 4096
    float* p_w1 = p_w0 + (size_t)DIM * 2 * DI;              // 2048 x 1024
    float* p_w2 = p_w1 + (size_t)DI * (DI / 2);             // 1024 x 2048
    float* p_w3 = p_w2 + (size_t)(DI / 2) * DI;             // 2048 x 1024

    cudaFuncSetAttribute(tgemm_kernel<0>, cudaFuncAttributeMaxDynamicSharedMemorySize, SMEM_BYTES);
    cudaFuncSetAttribute(tgemm_kernel<1>, cudaFuncAttributeMaxDynamicSharedMemorySize, SMEM_BYTES);
    cudaFuncSetAttribute(tgemm_kernel<2>, cudaFuncAttributeMaxDynamicSharedMemorySize, SMEM_BYTES);
    cudaFuncSetAttribute(tgemm_kernel<3>, cudaFuncAttributeMaxDynamicSharedMemorySize, SMEM_BYTES);

    softmax3_kernel<<<1, 1>>>(scale_w);

    // 0) round GEMM operands to tf32 bits
    {
        int n4;
        n4 = ROWS_FULL * DIM / 4;
        cvt_tf32_kernel<<<(n4 + 255) / 256, 256>>>(x, p_xcvt, n4);
        n4 = DIM * 2 * DI / 4;
        cvt_tf32_kernel<<<(n4 + 255) / 256, 256>>>(in_proj, p_w0, n4);
        n4 = DI * (DI / 2) / 4;
        cvt_tf32_kernel<<<(n4 + 255) / 256, 256>>>(cg_w1, p_w1, n4);
        n4 = (DI / 2) * DI / 4;
        cvt_tf32_kernel<<<(n4 + 255) / 256, 256>>>(cg_w2, p_w2, n4);
        n4 = DI * DIM / 4;
        cvt_tf32_kernel<<<(n4 + 255) / 256, 256>>>(out_proj, p_w3, n4);
    }

    // 1) xz = x @ in_proj_w   (16384 x 4096, K=1024)
    {
        dim3 grid(2 * DI / 128, ROWS_FULL / 128);
        tgemm_kernel<0><<<grid, 256, SMEM_BYTES>>>(p_xcvt, p_w0, p_xz,
                                                   ROWS_FULL, 2 * DI, DIM, nullptr, nullptr);
    }

    // 2) per-scale SSM path (downsample fused into conv / ssm_pw; bssm via tensor GEMM)
    float* ys_bufs[NSCALES] = {p_ys0, p_ys1, p_ys2};
    for (int s = 0; s < NSCALES; s++) {
        int stride = 1 << s;
        int Ts = T_LEN / stride;
        int rows = BATCH * Ts;
        int total = rows * DI;
        conv_silu_kernel<<<(total + 255) / 256, 256>>>(p_xz,
                                                       conv_w + (size_t)s * DI * KCONV,
                                                       conv_b + (size_t)s * DI,
                                                       p_xc, Ts, stride);
        {
            int np = DI * 128;
            pad_xproj_kernel<<<(np + 255) / 256, 256>>>(xproj_w + (size_t)s * DI * 2 * DSTATE,
                                                        p_bpad);
            dim3 grid(1, rows / 128);
            tgemm_kernel<0><<<grid, 256, SMEM_BYTES>>>(p_xc, p_bpad, p_bssm,
                                                       rows, 128, DI, nullptr, nullptr);
        }
        ssm_pw_kernel<<<rows, 256>>>(p_xc, p_bssm,
                                     dtproj_w + (size_t)s * DSTATE * DI,
                                     dtproj_b + (size_t)s * DI,
                                     D_param + (size_t)s * DI,
                                     p_xz, Ts, stride, ys_bufs[s]);
    }

    // 2b) merged upsample + fuse
    {
        int total4 = ROWS_FULL * (DI / 4);
        ups_fuse_kernel<<<(total4 + 255) / 256, 256>>>(p_ys0, p_ys1, p_ys2, p_fused, p_ctx);
    }

    // 3) h = tf32(silu(ctx @ cg_w1))   (16384 x 1024, K=2048)
    {
        dim3 grid((DI / 2) / 128, ROWS_FULL / 128);
        tgemm_kernel<1><<<grid, 256, SMEM_BYTES>>>(p_ctx, p_w1, p_h,
                                                   ROWS_FULL, DI / 2, DI, nullptr, nullptr);
    }
    // 4) mm_in = tf32(fused * sigmoid(h @ cg_w2) * silu(gate))  (16384 x 2048, K=1024)
    {
        dim3 grid(DI / 128, ROWS_FULL / 128);
        tgemm_kernel<2><<<grid, 256, SMEM_BYTES>>>(p_h, p_w2, p_mmin,
                                                   ROWS_FULL, DI, DI / 2, p_fused, p_xz + DI);
    }
    // 5) preln = mm_in @ out_proj + x   (16384 x 1024, K=2048)
    {
        dim3 grid(DIM / 128, ROWS_FULL / 128);
        tgemm_kernel<3><<<grid, 256, SMEM_BYTES>>>(p_mmin, p_w3, p_preln,
                                                   ROWS_FULL, DIM, DI, x, nullptr);
    }
    // 6) LayerNorm -> out
    ln_kernel<<<ROWS_FULL, 256>>>(p_preln, ln_g, ln_b, out);
}